// round 8
// baseline (speedup 1.0000x reference)
#include <cuda_runtime.h>

#define TT 1024
#define EE 256
#define DD 64
#define BB 2
#define JCH 64        // keys per chunk
#define PROWS 8       // rows per proj block (grid = 256 > 148 SMs)

// Scratch (device globals: no allocation allowed in kernel_launch)
__device__ float g_qpb[BB * TT * DD];   // qp + b1, row-major [row][d]
__device__ float g_kpT[BB * DD * TT];   // kp transposed   [b][d][t]
__device__ float g_v  [BB * TT * DD];   // v, row-major    [row][dv]
// split-K partials
__device__ float g_po[2][BB * TT * DD]; // unnormalized o
__device__ float g_pm[2][BB * TT];      // running max
__device__ float g_pl[2][BB * TT];      // denominator

__device__ __forceinline__ void cp16(float* dst, const float* src) {
    unsigned d = (unsigned)__cvta_generic_to_shared(dst);
    asm volatile("cp.async.cg.shared.global [%0], [%1], 16;" :: "r"(d), "l"(src));
}
__device__ __forceinline__ void cp_commit() { asm volatile("cp.async.commit_group;"); }
__device__ __forceinline__ void cp_wait_all() { asm volatile("cp.async.wait_group 0;"); }

// Warp-wide float max via integer redux.sync (f32 redux doesn't exist).
__device__ __forceinline__ float warp_max_f32(float x) {
    unsigned ix = __float_as_uint(x);
    ix = (ix & 0x80000000u) ? ~ix : (ix | 0x80000000u);
    unsigned r = __reduce_max_sync(0xffffffffu, ix);
    r = (r & 0x80000000u) ? (r & 0x7fffffffu) : ~r;
    return __uint_as_float(r);
}

// ---------------------------------------------------------------------------
// Kernel 1: fused projections. 8 rows/block x 256 blocks x 192 threads.
// e-loop chunked by 8 with explicit weight prefetch (MLP=8).
// Thread = (which[3], d4[16], rg[4]): 2 rows x 4 cols.
// ---------------------------------------------------------------------------
__global__ __launch_bounds__(192) void proj_kernel(
    const float* __restrict__ x,
    const float* __restrict__ Wq, const float* __restrict__ bq,
    const float* __restrict__ Wk, const float* __restrict__ bk,
    const float* __restrict__ Wv, const float* __restrict__ bv,
    const float* __restrict__ W1, const float* __restrict__ b1)
{
    __shared__ float x_s[PROWS][EE];   // 8KB
    __shared__ float q_s[PROWS][DD];   // 2KB
    __shared__ float k_s[PROWS][DD];   // 2KB

    const int r0 = blockIdx.x * PROWS;
    const int t  = threadIdx.x;

    for (int idx = t; idx < PROWS * EE / 4; idx += 192)
        ((float4*)x_s)[idx] = ((const float4*)(x + r0 * EE))[idx];
    __syncthreads();

    // ---- Phase A: q,k,v. 2 rows x 4 cols per thread, 8-deep w prefetch ----
    {
        const int which = t >> 6;          // 0..2
        const int d4    = (t >> 2) & 15;   // 0..15
        const int ra    = (t & 3) * 2;     // rows ra, ra+1
        const float4* W4 = (const float4*)(which == 0 ? Wq : (which == 1 ? Wk : Wv));
        const float4* b4 = (const float4*)(which == 0 ? bq : (which == 1 ? bk : bv));

        float4 acc0 = make_float4(0.f, 0.f, 0.f, 0.f);
        float4 acc1 = make_float4(0.f, 0.f, 0.f, 0.f);

        for (int e0 = 0; e0 < EE; e0 += 8) {
            float4 w[8];
            #pragma unroll
            for (int u = 0; u < 8; u++) w[u] = W4[(e0 + u) * 16 + d4];
            #pragma unroll
            for (int u = 0; u < 8; u++) {
                float x0 = x_s[ra    ][e0 + u];
                float x1 = x_s[ra + 1][e0 + u];
                acc0.x = fmaf(x0, w[u].x, acc0.x);
                acc0.y = fmaf(x0, w[u].y, acc0.y);
                acc0.z = fmaf(x0, w[u].z, acc0.z);
                acc0.w = fmaf(x0, w[u].w, acc0.w);
                acc1.x = fmaf(x1, w[u].x, acc1.x);
                acc1.y = fmaf(x1, w[u].y, acc1.y);
                acc1.z = fmaf(x1, w[u].z, acc1.z);
                acc1.w = fmaf(x1, w[u].w, acc1.w);
            }
        }
        float4 bias = b4[d4];
        float4 o0, o1;
        o0.x = acc0.x + bias.x; o0.y = acc0.y + bias.y;
        o0.z = acc0.z + bias.z; o0.w = acc0.w + bias.w;
        o1.x = acc1.x + bias.x; o1.y = acc1.y + bias.y;
        o1.z = acc1.z + bias.z; o1.w = acc1.w + bias.w;
        if (which == 2) {
            *(float4*)&g_v[(r0 + ra    ) * DD + d4 * 4] = o0;
            *(float4*)&g_v[(r0 + ra + 1) * DD + d4 * 4] = o1;
        } else {
            o0.x = fmaxf(o0.x, 0.f); o0.y = fmaxf(o0.y, 0.f);
            o0.z = fmaxf(o0.z, 0.f); o0.w = fmaxf(o0.w, 0.f);
            o1.x = fmaxf(o1.x, 0.f); o1.y = fmaxf(o1.y, 0.f);
            o1.z = fmaxf(o1.z, 0.f); o1.w = fmaxf(o1.w, 0.f);
            if (which == 0) {
                *(float4*)&q_s[ra    ][d4 * 4] = o0;
                *(float4*)&q_s[ra + 1][d4 * 4] = o1;
            } else {
                *(float4*)&k_s[ra    ][d4 * 4] = o0;
                *(float4*)&k_s[ra + 1][d4 * 4] = o1;
            }
        }
    }
    __syncthreads();

    // ---- Phase B: qp (with b1) and kp. 2 rows x 4 cols, 8-deep prefetch ----
    if (t < 128) {
        const int sel = t >> 6;            // 0 = qp, 1 = kp
        const int d4  = (t >> 2) & 15;
        const int ra  = (t & 3) * 2;

        const float (*src)[DD] = (sel == 0) ? q_s : k_s;
        const float4* W14 = (const float4*)W1 + sel * 64 * 16;

        float4 acc0 = make_float4(0.f, 0.f, 0.f, 0.f);
        float4 acc1 = make_float4(0.f, 0.f, 0.f, 0.f);

        for (int e0 = 0; e0 < DD; e0 += 8) {
            float4 w[8];
            #pragma unroll
            for (int u = 0; u < 8; u++) w[u] = W14[(e0 + u) * 16 + d4];
            #pragma unroll
            for (int u = 0; u < 8; u++) {
                float x0 = src[ra    ][e0 + u];
                float x1 = src[ra + 1][e0 + u];
                acc0.x = fmaf(x0, w[u].x, acc0.x);
                acc0.y = fmaf(x0, w[u].y, acc0.y);
                acc0.z = fmaf(x0, w[u].z, acc0.z);
                acc0.w = fmaf(x0, w[u].w, acc0.w);
                acc1.x = fmaf(x1, w[u].x, acc1.x);
                acc1.y = fmaf(x1, w[u].y, acc1.y);
                acc1.z = fmaf(x1, w[u].z, acc1.z);
                acc1.w = fmaf(x1, w[u].w, acc1.w);
            }
        }

        if (sel == 0) {
            float4 bias = ((const float4*)b1)[d4];
            float4 o0, o1;
            o0.x = acc0.x + bias.x; o0.y = acc0.y + bias.y;
            o0.z = acc0.z + bias.z; o0.w = acc0.w + bias.w;
            o1.x = acc1.x + bias.x; o1.y = acc1.y + bias.y;
            o1.z = acc1.z + bias.z; o1.w = acc1.w + bias.w;
            *(float4*)&g_qpb[(r0 + ra    ) * DD + d4 * 4] = o0;
            *(float4*)&g_qpb[(r0 + ra + 1) * DD + d4 * 4] = o1;
        } else {
            const int b  = r0 >> 10;
            const int tb = (r0 & 1023) + ra;          // 2 consecutive t-rows
            *(float2*)&g_kpT[(b * DD + d4 * 4 + 0) * TT + tb] = make_float2(acc0.x, acc1.x);
            *(float2*)&g_kpT[(b * DD + d4 * 4 + 1) * TT + tb] = make_float2(acc0.y, acc1.y);
            *(float2*)&g_kpT[(b * DD + d4 * 4 + 2) * TT + tb] = make_float2(acc0.z, acc1.z);
            *(float2*)&g_kpT[(b * DD + d4 * 4 + 3) * TT + tb] = make_float2(acc0.w, acc1.w);
        }
    }
}

// ---------------------------------------------------------------------------
// Kernel 2: split-K attention partials (unchanged from R7).
// ---------------------------------------------------------------------------
#define SMEM_FLOATS (2 * DD * JCH + 2 * JCH * DD + 4 * JCH + 4 * DD + DD + 4)
#define SMEM_BYTES  (SMEM_FLOATS * 4)

__global__ __launch_bounds__(64, 3) void attn_kernel(
    const float* __restrict__ W2)
{
    extern __shared__ __align__(16) float smem[];
    float (*kp_s)[DD][JCH] = (float (*)[DD][JCH])smem;                  // [2][d][j]
    float (*v_s)[JCH][DD]  = (float (*)[JCH][DD])(smem + 2 * DD * JCH); // [2][j][dv]
    float (*p_s)[JCH]      = (float (*)[JCH])(smem + 4 * DD * JCH);     // [4][j]
    float (*q_s)[DD]       = (float (*)[DD])(smem + 4 * DD * JCH + 4 * JCH); // [4][d]
    float *w2_s            = smem + 4 * DD * JCH + 4 * JCH + 4 * DD;

    const int bid  = (int)blockIdx.x;
    const int quad = ((int)gridDim.x / 2 - 1) - (bid >> 1);   // heavy-first
    const int s    = bid & 1;                                  // split id
    const int b    = quad >> 8;
    const int i0   = (quad & 255) * 4;
    const int t    = threadIdx.x;
    const int wid  = t >> 5;
    const int lane = t & 31;
    const int ia   = i0 + wid * 2;
    const int ib   = ia + 1;

    if (t < DD) w2_s[t] = W2[t];
    ((float4*)q_s)[t] = ((const float4*)(g_qpb + (b * TT + i0) * DD))[t];

    const float* kpT_b = g_kpT + b * DD * TT;
    const float* v_b   = g_v   + b * TT * DD;

    const int nch = i0 / JCH + 1;            // block-uniform

    if (s < nch) {
        const int j0 = s * JCH;
        #pragma unroll
        for (int u = 0; u < 16; u++) {
            int idx = t + u * 64;
            int d = idx >> 4, cc = idx & 15;
            cp16(&kp_s[0][d][cc * 4], kpT_b + d * TT + j0 + cc * 4);
            cp16(&v_s[0][0][0] + idx * 4, v_b + j0 * DD + idx * 4);
        }
    }
    cp_commit();

    const float NEG_INF = __int_as_float(0xff800000);
    float ma = NEG_INF, la = 0.f, mb = NEG_INF, lb = 0.f;
    float axe = 0.f, aye = 0.f, axo = 0.f, ayo = 0.f;
    float bxe = 0.f, bye = 0.f, bxo = 0.f, byo = 0.f;

    const float4* qa4 = (const float4*)q_s[wid * 2];
    const float4* qb4 = (const float4*)q_s[wid * 2 + 1];
    const float4* w24 = (const float4*)w2_s;

    for (int c = s; c < nch; c += 2) {
        cp_wait_all();
        __syncthreads();

        if (c + 2 < nch) {
            const int j0n = (c + 2) * JCH;
            const int buf = ((c >> 1) + 1) & 1;
            #pragma unroll
            for (int u = 0; u < 16; u++) {
                int idx = t + u * 64;
                int d = idx >> 4, cc = idx & 15;
                cp16(&kp_s[buf][d][cc * 4], kpT_b + d * TT + j0n + cc * 4);
                cp16(&v_s[buf][0][0] + idx * 4, v_b + j0n * DD + idx * 4);
            }
            cp_commit();
        }

        const int j0 = c * JCH;
        const int cb2 = (c >> 1) & 1;
        const float (*kp)[JCH] = kp_s[cb2];
        const float (*vv_s)[DD] = v_s[cb2];

        float a0 = 0.f, a1 = 0.f, a2 = 0.f, a3 = 0.f;
        float b0 = 0.f, b1 = 0.f, b2 = 0.f, b3 = 0.f;
        #pragma unroll
        for (int d4 = 0; d4 < 16; d4++) {
            float4 w4 = w24[d4];
            float4 qa = qa4[d4];
            float4 qb = qb4[d4];
            float2 k0 = *(const float2*)&kp[4 * d4 + 0][2 * lane];
            float2 k1 = *(const float2*)&kp[4 * d4 + 1][2 * lane];
            float2 k2 = *(const float2*)&kp[4 * d4 + 2][2 * lane];
            float2 k3 = *(const float2*)&kp[4 * d4 + 3][2 * lane];
            a0 = fmaf(fmaxf(qa.x + k0.x, 0.f), w4.x, a0);
            a1 = fmaf(fmaxf(qa.x + k0.y, 0.f), w4.x, a1);
            a2 = fmaf(fmaxf(qa.y + k1.x, 0.f), w4.y, a2);
            a3 = fmaf(fmaxf(qa.y + k1.y, 0.f), w4.y, a3);
            a0 = fmaf(fmaxf(qa.z + k2.x, 0.f), w4.z, a0);
            a1 = fmaf(fmaxf(qa.z + k2.y, 0.f), w4.z, a1);
            a2 = fmaf(fmaxf(qa.w + k3.x, 0.f), w4.w, a2);
            a3 = fmaf(fmaxf(qa.w + k3.y, 0.f), w4.w, a3);
            b0 = fmaf(fmaxf(qb.x + k0.x, 0.f), w4.x, b0);
            b1 = fmaf(fmaxf(qb.x + k0.y, 0.f), w4.x, b1);
            b2 = fmaf(fmaxf(qb.y + k1.x, 0.f), w4.y, b2);
            b3 = fmaf(fmaxf(qb.y + k1.y, 0.f), w4.y, b3);
            b0 = fmaf(fmaxf(qb.z + k2.x, 0.f), w4.z, b0);
            b1 = fmaf(fmaxf(qb.z + k2.y, 0.f), w4.z, b1);
            b2 = fmaf(fmaxf(qb.w + k3.x, 0.f), w4.w, b2);
            b3 = fmaf(fmaxf(qb.w + k3.y, 0.f), w4.w, b3);
        }
        const int j = j0 + 2 * lane;
        float s0a = (j     <= ia) ? (a0 + a2) : NEG_INF;
        float s1a = (j + 1 <= ia) ? (a1 + a3) : NEG_INF;
        float s0b = (j     <= ib) ? (b0 + b2) : NEG_INF;
        float s1b = (j + 1 <= ib) ? (b1 + b3) : NEG_INF;

        float nma  = fmaxf(ma, warp_max_f32(fmaxf(s0a, s1a)));
        float nmb  = fmaxf(mb, warp_max_f32(fmaxf(s0b, s1b)));
        float ca   = __expf(ma - nma);
        float cb   = __expf(mb - nmb);
        float p0a  = __expf(s0a - nma), p1a = __expf(s1a - nma);
        float p0b  = __expf(s0b - nmb), p1b = __expf(s1b - nmb);
        la = fmaf(la, ca, p0a + p1a);
        lb = fmaf(lb, cb, p0b + p1b);
        axe *= ca; aye *= ca; axo *= ca; ayo *= ca;
        bxe *= cb; bye *= cb; bxo *= cb; byo *= cb;
        ma = nma; mb = nmb;

        *(float2*)&p_s[wid * 2    ][2 * lane] = make_float2(p0a, p1a);
        *(float2*)&p_s[wid * 2 + 1][2 * lane] = make_float2(p0b, p1b);
        __syncwarp();

        #pragma unroll
        for (int jj = 0; jj < JCH; jj += 2) {
            float  pae = p_s[wid * 2][jj];
            float  pao = p_s[wid * 2][jj + 1];
            float  pbe = p_s[wid * 2 + 1][jj];
            float  pbo = p_s[wid * 2 + 1][jj + 1];
            float2 ve = *(const float2*)&vv_s[jj][2 * lane];
            float2 vo = *(const float2*)&vv_s[jj + 1][2 * lane];
            axe = fmaf(pae, ve.x, axe);
            aye = fmaf(pae, ve.y, aye);
            axo = fmaf(pao, vo.x, axo);
            ayo = fmaf(pao, vo.y, ayo);
            bxe = fmaf(pbe, ve.x, bxe);
            bye = fmaf(pbe, ve.y, bye);
            bxo = fmaf(pbo, vo.x, bxo);
            byo = fmaf(pbo, vo.y, byo);
        }
    }

    float lta = la, ltb = lb;
    #pragma unroll
    for (int off = 16; off; off >>= 1) {
        lta += __shfl_xor_sync(0xffffffffu, lta, off);
        ltb += __shfl_xor_sync(0xffffffffu, ltb, off);
    }

    *(float2*)&g_po[s][(b * TT + ia) * DD + 2 * lane] = make_float2(axe + axo, aye + ayo);
    *(float2*)&g_po[s][(b * TT + ib) * DD + 2 * lane] = make_float2(bxe + bxo, bye + byo);
    if (lane == 0) {
        g_pm[s][b * TT + ia] = ma;  g_pl[s][b * TT + ia] = lta;
        g_pm[s][b * TT + ib] = mb;  g_pl[s][b * TT + ib] = ltb;
    }
}

// ---------------------------------------------------------------------------
// Kernel 3: combine the two split-K partials. 4 rows/block x 512 blocks.
// ---------------------------------------------------------------------------
__global__ __launch_bounds__(128) void combine_kernel(float* __restrict__ out)
{
    const int row  = blockIdx.x * 4 + (threadIdx.x >> 5);
    const int lane = threadIdx.x & 31;

    float m0 = g_pm[0][row], l0 = g_pl[0][row];
    float m1 = g_pm[1][row], l1 = g_pl[1][row];
    float M  = fmaxf(m0, m1);
    float c0 = __expf(m0 - M);
    float c1 = __expf(m1 - M);          // m1=-inf (empty split) -> c1=0
    float inv = 1.0f / fmaf(l0, c0, l1 * c1);

    float2 o0 = *(const float2*)&g_po[0][row * DD + 2 * lane];
    float2 o1 = *(const float2*)&g_po[1][row * DD + 2 * lane];
    *(float2*)&out[row * DD + 2 * lane] =
        make_float2(fmaf(o0.x, c0, o1.x * c1) * inv,
                    fmaf(o0.y, c0, o1.y * c1) * inv);
}

// ---------------------------------------------------------------------------
extern "C" void kernel_launch(void* const* d_in, const int* in_sizes, int n_in,
                              void* d_out, int out_size)
{
    const float* x  = (const float*)d_in[0];
    const float* Wq = (const float*)d_in[1];
    const float* bq = (const float*)d_in[2];
    const float* Wk = (const float*)d_in[3];
    const float* bk = (const float*)d_in[4];
    const float* Wv = (const float*)d_in[5];
    const float* bv = (const float*)d_in[6];
    const float* W1 = (const float*)d_in[7];
    const float* b1 = (const float*)d_in[8];
    const float* W2 = (const float*)d_in[9];
    // b2 (d_in[10]) is a constant shift on scores: cancels in softmax.

    (void)cudaFuncSetAttribute(attn_kernel,
                               cudaFuncAttributeMaxDynamicSharedMemorySize,
                               SMEM_BYTES);

    proj_kernel<<<BB * TT / PROWS, 192>>>(x, Wq, bq, Wk, bk, Wv, bv, W1, b1);
    attn_kernel<<<BB * TT / 4 * 2, 64, SMEM_BYTES>>>(W2);
    combine_kernel<<<BB * TT / 4, 128>>>((float*)d_out);
}

// round 9
// speedup vs baseline: 1.2535x; 1.2535x over previous
#include <cuda_runtime.h>

#define TT 1024
#define EE 256
#define DD 64
#define BB 2
#define JCH 64        // keys per chunk (attn)
#define PROWS 8       // rows per proj block (grid = 256)
#define PCH 32        // e-rows per proj weight chunk
#define NPCH (EE / PCH)

// Scratch (device globals: no allocation allowed in kernel_launch)
__device__ float g_qpb[BB * TT * DD];   // qp + b1, row-major [row][d]
__device__ float g_kpT[BB * DD * TT];   // kp transposed   [b][d][t]
__device__ float g_v  [BB * TT * DD];   // v, row-major    [row][dv]
// split-K partials
__device__ float g_po[2][BB * TT * DD]; // unnormalized o
__device__ float g_pm[2][BB * TT];      // running max
__device__ float g_pl[2][BB * TT];      // denominator

__device__ __forceinline__ void cp16(float* dst, const float* src) {
    unsigned d = (unsigned)__cvta_generic_to_shared(dst);
    asm volatile("cp.async.cg.shared.global [%0], [%1], 16;" :: "r"(d), "l"(src));
}
__device__ __forceinline__ void cp_commit() { asm volatile("cp.async.commit_group;"); }
template <int N>
__device__ __forceinline__ void cp_wait() { asm volatile("cp.async.wait_group %0;" :: "n"(N)); }

// Warp-wide float max via integer redux.sync (f32 redux doesn't exist).
__device__ __forceinline__ float warp_max_f32(float x) {
    unsigned ix = __float_as_uint(x);
    ix = (ix & 0x80000000u) ? ~ix : (ix | 0x80000000u);
    unsigned r = __reduce_max_sync(0xffffffffu, ix);
    r = (r & 0x80000000u) ? (r & 0x7fffffffu) : ~r;
    return __uint_as_float(r);
}

// ---------------------------------------------------------------------------
// Kernel 1 (v3): projections with cp.async-staged weights.
// 8 rows/block x 256 blocks x 192 threads.
// Phase A: thread=(which[3],d4[16],rg[4]) -> 2 rows x 4 cols, weights from
// double-buffered smem chunks. Phase B: W1 staged once at start.
// ---------------------------------------------------------------------------
// dynamic smem layout (floats):
//   x_sT   [EE][PROWS]          2048
//   w_s    [2][PCH][192]       12288
//   w1_s   [128][64]            8192
//   q_sT   [DD][PROWS]           512
//   k_sT   [DD][PROWS]           512
#define PX   0
#define PW   (PX + EE * PROWS)
#define PW1  (PW + 2 * PCH * 192)
#define PQ   (PW1 + 128 * 64)
#define PK   (PQ + DD * PROWS)
#define PROJ_SMEM_FLOATS (PK + DD * PROWS)
#define PROJ_SMEM_BYTES  (PROJ_SMEM_FLOATS * 4)

__global__ __launch_bounds__(192) void proj_kernel(
    const float* __restrict__ x,
    const float* __restrict__ Wq, const float* __restrict__ bq,
    const float* __restrict__ Wk, const float* __restrict__ bk,
    const float* __restrict__ Wv, const float* __restrict__ bv,
    const float* __restrict__ W1, const float* __restrict__ b1)
{
    extern __shared__ __align__(16) float sm[];
    float* x_sT = sm + PX;        // [e][row]
    float* w_s  = sm + PW;        // [buf][e][col(192)]
    float* w1_s = sm + PW1;       // [row(128)][col(64)]
    float* q_sT = sm + PQ;        // [dd][row]
    float* k_sT = sm + PK;        // [dd][row]

    const int r0 = blockIdx.x * PROWS;
    const int t  = threadIdx.x;

    const float* Wmat[3] = { Wq, Wk, Wv };

    // --- async stage: W1 (whole) + weight chunk 0 -> group G0 ---
    for (int idx = t; idx < 2048; idx += 192)
        cp16(&w1_s[idx * 4], W1 + idx * 4);
    {
        #pragma unroll
        for (int u = 0; u < 8; u++) {
            int idx = t + u * 192;               // 0..1535
            int row = idx / 48, col4 = idx % 48;
            int which = col4 >> 4, c4 = col4 & 15;
            cp16(&w_s[row * 192 + col4 * 4],
                 Wmat[which] + (row * 16 + c4) * 4);
        }
    }
    cp_commit();

    // --- stage x transposed: x_sT[e][row] ---
    {
        const float4* x4 = (const float4*)(x + r0 * EE);
        for (int idx = t; idx < PROWS * EE / 4; idx += 192) {
            int row = idx >> 6, e4 = idx & 63;
            float4 v = x4[row * 64 + e4];
            x_sT[(e4 * 4 + 0) * PROWS + row] = v.x;
            x_sT[(e4 * 4 + 1) * PROWS + row] = v.y;
            x_sT[(e4 * 4 + 2) * PROWS + row] = v.z;
            x_sT[(e4 * 4 + 3) * PROWS + row] = v.w;
        }
    }

    // --- Phase A over 8 chunks, double-buffered ---
    const int which = t >> 6;          // 0..2
    const int d4    = (t >> 2) & 15;   // 0..15
    const int ra    = (t & 3) * 2;     // rows ra, ra+1

    float4 acc0 = make_float4(0.f, 0.f, 0.f, 0.f);
    float4 acc1 = make_float4(0.f, 0.f, 0.f, 0.f);

    for (int c = 0; c < NPCH; c++) {
        if (c + 1 < NPCH) {
            const int e0n = (c + 1) * PCH;
            float* dstbuf = w_s + ((c + 1) & 1) * PCH * 192;
            #pragma unroll
            for (int u = 0; u < 8; u++) {
                int idx = t + u * 192;
                int row = idx / 48, col4 = idx % 48;
                int wch = col4 >> 4, c4 = col4 & 15;
                cp16(&dstbuf[row * 192 + col4 * 4],
                     Wmat[wch] + ((e0n + row) * 16 + c4) * 4);
            }
            cp_commit();
            cp_wait<1>();
        } else {
            cp_wait<0>();
        }
        __syncthreads();                     // chunk c visible (+ x_sT on c=0)

        const float* wb = w_s + (c & 1) * PCH * 192 + which * 64 + d4 * 4;
        const float* xb = x_sT + c * PCH * PROWS + ra;
        #pragma unroll
        for (int e = 0; e < PCH; e++) {
            float4 w4 = *(const float4*)(wb + e * 192);
            float2 x2 = *(const float2*)(xb + e * PROWS);
            acc0.x = fmaf(x2.x, w4.x, acc0.x);
            acc0.y = fmaf(x2.x, w4.y, acc0.y);
            acc0.z = fmaf(x2.x, w4.z, acc0.z);
            acc0.w = fmaf(x2.x, w4.w, acc0.w);
            acc1.x = fmaf(x2.y, w4.x, acc1.x);
            acc1.y = fmaf(x2.y, w4.y, acc1.y);
            acc1.z = fmaf(x2.y, w4.z, acc1.z);
            acc1.w = fmaf(x2.y, w4.w, acc1.w);
        }
        __syncthreads();                     // done reading buf before overwrite
    }

    // --- Phase A epilogue: bias (+relu), write v / q_sT / k_sT ---
    {
        const float* bias3 = (which == 0) ? bq : (which == 1 ? bk : bv);
        float4 bias = ((const float4*)bias3)[d4];
        float4 o0, o1;
        o0.x = acc0.x + bias.x; o0.y = acc0.y + bias.y;
        o0.z = acc0.z + bias.z; o0.w = acc0.w + bias.w;
        o1.x = acc1.x + bias.x; o1.y = acc1.y + bias.y;
        o1.z = acc1.z + bias.z; o1.w = acc1.w + bias.w;
        if (which == 2) {
            *(float4*)&g_v[(r0 + ra    ) * DD + d4 * 4] = o0;
            *(float4*)&g_v[(r0 + ra + 1) * DD + d4 * 4] = o1;
        } else {
            float* dst = (which == 0) ? q_sT : k_sT;
            dst[(d4 * 4 + 0) * PROWS + ra]     = fmaxf(o0.x, 0.f);
            dst[(d4 * 4 + 1) * PROWS + ra]     = fmaxf(o0.y, 0.f);
            dst[(d4 * 4 + 2) * PROWS + ra]     = fmaxf(o0.z, 0.f);
            dst[(d4 * 4 + 3) * PROWS + ra]     = fmaxf(o0.w, 0.f);
            dst[(d4 * 4 + 0) * PROWS + ra + 1] = fmaxf(o1.x, 0.f);
            dst[(d4 * 4 + 1) * PROWS + ra + 1] = fmaxf(o1.y, 0.f);
            dst[(d4 * 4 + 2) * PROWS + ra + 1] = fmaxf(o1.z, 0.f);
            dst[(d4 * 4 + 3) * PROWS + ra + 1] = fmaxf(o1.w, 0.f);
        }
    }
    __syncthreads();

    // --- Phase B: qp (with b1) and kp from smem-staged W1 ---
    if (t < 128) {
        const int sel = t >> 6;            // 0 = qp, 1 = kp
        const int d4b = (t >> 2) & 15;
        const int rb  = (t & 3) * 2;

        const float* srcT = (sel == 0) ? q_sT : k_sT;
        const float* wb   = w1_s + (sel * 64) * 64 + d4b * 4;

        float4 a0 = make_float4(0.f, 0.f, 0.f, 0.f);
        float4 a1 = make_float4(0.f, 0.f, 0.f, 0.f);

        #pragma unroll 16
        for (int e = 0; e < DD; e++) {
            float4 w4 = *(const float4*)(wb + e * 64);
            float2 x2 = *(const float2*)(srcT + e * PROWS + rb);
            a0.x = fmaf(x2.x, w4.x, a0.x);
            a0.y = fmaf(x2.x, w4.y, a0.y);
            a0.z = fmaf(x2.x, w4.z, a0.z);
            a0.w = fmaf(x2.x, w4.w, a0.w);
            a1.x = fmaf(x2.y, w4.x, a1.x);
            a1.y = fmaf(x2.y, w4.y, a1.y);
            a1.z = fmaf(x2.y, w4.z, a1.z);
            a1.w = fmaf(x2.y, w4.w, a1.w);
        }

        if (sel == 0) {
            float4 bias = ((const float4*)b1)[d4b];
            float4 o0, o1;
            o0.x = a0.x + bias.x; o0.y = a0.y + bias.y;
            o0.z = a0.z + bias.z; o0.w = a0.w + bias.w;
            o1.x = a1.x + bias.x; o1.y = a1.y + bias.y;
            o1.z = a1.z + bias.z; o1.w = a1.w + bias.w;
            *(float4*)&g_qpb[(r0 + rb    ) * DD + d4b * 4] = o0;
            *(float4*)&g_qpb[(r0 + rb + 1) * DD + d4b * 4] = o1;
        } else {
            const int b  = r0 >> 10;
            const int tb = (r0 & 1023) + rb;
            *(float2*)&g_kpT[(b * DD + d4b * 4 + 0) * TT + tb] = make_float2(a0.x, a1.x);
            *(float2*)&g_kpT[(b * DD + d4b * 4 + 1) * TT + tb] = make_float2(a0.y, a1.y);
            *(float2*)&g_kpT[(b * DD + d4b * 4 + 2) * TT + tb] = make_float2(a0.z, a1.z);
            *(float2*)&g_kpT[(b * DD + d4b * 4 + 3) * TT + tb] = make_float2(a0.w, a1.w);
        }
    }
}

// ---------------------------------------------------------------------------
// Kernel 2: split-K attention partials (unchanged from R7/R8).
// ---------------------------------------------------------------------------
#define SMEM_FLOATS (2 * DD * JCH + 2 * JCH * DD + 4 * JCH + 4 * DD + DD + 4)
#define SMEM_BYTES  (SMEM_FLOATS * 4)

__global__ __launch_bounds__(64, 3) void attn_kernel(
    const float* __restrict__ W2)
{
    extern __shared__ __align__(16) float smem[];
    float (*kp_s)[DD][JCH] = (float (*)[DD][JCH])smem;
    float (*v_s)[JCH][DD]  = (float (*)[JCH][DD])(smem + 2 * DD * JCH);
    float (*p_s)[JCH]      = (float (*)[JCH])(smem + 4 * DD * JCH);
    float (*q_s)[DD]       = (float (*)[DD])(smem + 4 * DD * JCH + 4 * JCH);
    float *w2_s            = smem + 4 * DD * JCH + 4 * JCH + 4 * DD;

    const int bid  = (int)blockIdx.x;
    const int quad = ((int)gridDim.x / 2 - 1) - (bid >> 1);
    const int s    = bid & 1;
    const int b    = quad >> 8;
    const int i0   = (quad & 255) * 4;
    const int t    = threadIdx.x;
    const int wid  = t >> 5;
    const int lane = t & 31;
    const int ia   = i0 + wid * 2;
    const int ib   = ia + 1;

    if (t < DD) w2_s[t] = W2[t];
    ((float4*)q_s)[t] = ((const float4*)(g_qpb + (b * TT + i0) * DD))[t];

    const float* kpT_b = g_kpT + b * DD * TT;
    const float* v_b   = g_v   + b * TT * DD;

    const int nch = i0 / JCH + 1;

    if (s < nch) {
        const int j0 = s * JCH;
        #pragma unroll
        for (int u = 0; u < 16; u++) {
            int idx = t + u * 64;
            int d = idx >> 4, cc = idx & 15;
            cp16(&kp_s[0][d][cc * 4], kpT_b + d * TT + j0 + cc * 4);
            cp16(&v_s[0][0][0] + idx * 4, v_b + j0 * DD + idx * 4);
        }
    }
    cp_commit();

    const float NEG_INF = __int_as_float(0xff800000);
    float ma = NEG_INF, la = 0.f, mb = NEG_INF, lb = 0.f;
    float axe = 0.f, aye = 0.f, axo = 0.f, ayo = 0.f;
    float bxe = 0.f, bye = 0.f, bxo = 0.f, byo = 0.f;

    const float4* qa4 = (const float4*)q_s[wid * 2];
    const float4* qb4 = (const float4*)q_s[wid * 2 + 1];
    const float4* w24 = (const float4*)w2_s;

    for (int c = s; c < nch; c += 2) {
        cp_wait<0>();
        __syncthreads();

        if (c + 2 < nch) {
            const int j0n = (c + 2) * JCH;
            const int buf = ((c >> 1) + 1) & 1;
            #pragma unroll
            for (int u = 0; u < 16; u++) {
                int idx = t + u * 64;
                int d = idx >> 4, cc = idx & 15;
                cp16(&kp_s[buf][d][cc * 4], kpT_b + d * TT + j0n + cc * 4);
                cp16(&v_s[buf][0][0] + idx * 4, v_b + j0n * DD + idx * 4);
            }
            cp_commit();
        }

        const int j0 = c * JCH;
        const int cb2 = (c >> 1) & 1;
        const float (*kp)[JCH] = kp_s[cb2];
        const float (*vv_s)[DD] = v_s[cb2];

        float a0 = 0.f, a1 = 0.f, a2 = 0.f, a3 = 0.f;
        float b0 = 0.f, b1 = 0.f, b2 = 0.f, b3 = 0.f;
        #pragma unroll
        for (int d4 = 0; d4 < 16; d4++) {
            float4 w4 = w24[d4];
            float4 qa = qa4[d4];
            float4 qb = qb4[d4];
            float2 k0 = *(const float2*)&kp[4 * d4 + 0][2 * lane];
            float2 k1 = *(const float2*)&kp[4 * d4 + 1][2 * lane];
            float2 k2 = *(const float2*)&kp[4 * d4 + 2][2 * lane];
            float2 k3 = *(const float2*)&kp[4 * d4 + 3][2 * lane];
            a0 = fmaf(fmaxf(qa.x + k0.x, 0.f), w4.x, a0);
            a1 = fmaf(fmaxf(qa.x + k0.y, 0.f), w4.x, a1);
            a2 = fmaf(fmaxf(qa.y + k1.x, 0.f), w4.y, a2);
            a3 = fmaf(fmaxf(qa.y + k1.y, 0.f), w4.y, a3);
            a0 = fmaf(fmaxf(qa.z + k2.x, 0.f), w4.z, a0);
            a1 = fmaf(fmaxf(qa.z + k2.y, 0.f), w4.z, a1);
            a2 = fmaf(fmaxf(qa.w + k3.x, 0.f), w4.w, a2);
            a3 = fmaf(fmaxf(qa.w + k3.y, 0.f), w4.w, a3);
            b0 = fmaf(fmaxf(qb.x + k0.x, 0.f), w4.x, b0);
            b1 = fmaf(fmaxf(qb.x + k0.y, 0.f), w4.x, b1);
            b2 = fmaf(fmaxf(qb.y + k1.x, 0.f), w4.y, b2);
            b3 = fmaf(fmaxf(qb.y + k1.y, 0.f), w4.y, b3);
            b0 = fmaf(fmaxf(qb.z + k2.x, 0.f), w4.z, b0);
            b1 = fmaf(fmaxf(qb.z + k2.y, 0.f), w4.z, b1);
            b2 = fmaf(fmaxf(qb.w + k3.x, 0.f), w4.w, b2);
            b3 = fmaf(fmaxf(qb.w + k3.y, 0.f), w4.w, b3);
        }
        const int j = j0 + 2 * lane;
        float s0a = (j     <= ia) ? (a0 + a2) : NEG_INF;
        float s1a = (j + 1 <= ia) ? (a1 + a3) : NEG_INF;
        float s0b = (j     <= ib) ? (b0 + b2) : NEG_INF;
        float s1b = (j + 1 <= ib) ? (b1 + b3) : NEG_INF;

        float nma  = fmaxf(ma, warp_max_f32(fmaxf(s0a, s1a)));
        float nmb  = fmaxf(mb, warp_max_f32(fmaxf(s0b, s1b)));
        float ca   = __expf(ma - nma);
        float cb   = __expf(mb - nmb);
        float p0a  = __expf(s0a - nma), p1a = __expf(s1a - nma);
        float p0b  = __expf(s0b - nmb), p1b = __expf(s1b - nmb);
        la = fmaf(la, ca, p0a + p1a);
        lb = fmaf(lb, cb, p0b + p1b);
        axe *= ca; aye *= ca; axo *= ca; ayo *= ca;
        bxe *= cb; bye *= cb; bxo *= cb; byo *= cb;
        ma = nma; mb = nmb;

        *(float2*)&p_s[wid * 2    ][2 * lane] = make_float2(p0a, p1a);
        *(float2*)&p_s[wid * 2 + 1][2 * lane] = make_float2(p0b, p1b);
        __syncwarp();

        #pragma unroll
        for (int jj = 0; jj < JCH; jj += 2) {
            float  pae = p_s[wid * 2][jj];
            float  pao = p_s[wid * 2][jj + 1];
            float  pbe = p_s[wid * 2 + 1][jj];
            float  pbo = p_s[wid * 2 + 1][jj + 1];
            float2 ve = *(const float2*)&vv_s[jj][2 * lane];
            float2 vo = *(const float2*)&vv_s[jj + 1][2 * lane];
            axe = fmaf(pae, ve.x, axe);
            aye = fmaf(pae, ve.y, aye);
            axo = fmaf(pao, vo.x, axo);
            ayo = fmaf(pao, vo.y, ayo);
            bxe = fmaf(pbe, ve.x, bxe);
            bye = fmaf(pbe, ve.y, bye);
            bxo = fmaf(pbo, vo.x, bxo);
            byo = fmaf(pbo, vo.y, byo);
        }
    }

    float lta = la, ltb = lb;
    #pragma unroll
    for (int off = 16; off; off >>= 1) {
        lta += __shfl_xor_sync(0xffffffffu, lta, off);
        ltb += __shfl_xor_sync(0xffffffffu, ltb, off);
    }

    *(float2*)&g_po[s][(b * TT + ia) * DD + 2 * lane] = make_float2(axe + axo, aye + ayo);
    *(float2*)&g_po[s][(b * TT + ib) * DD + 2 * lane] = make_float2(bxe + bxo, bye + byo);
    if (lane == 0) {
        g_pm[s][b * TT + ia] = ma;  g_pl[s][b * TT + ia] = lta;
        g_pm[s][b * TT + ib] = mb;  g_pl[s][b * TT + ib] = ltb;
    }
}

// ---------------------------------------------------------------------------
// Kernel 3: combine the two split-K partials.
// ---------------------------------------------------------------------------
__global__ __launch_bounds__(128) void combine_kernel(float* __restrict__ out)
{
    const int row  = blockIdx.x * 4 + (threadIdx.x >> 5);
    const int lane = threadIdx.x & 31;

    float m0 = g_pm[0][row], l0 = g_pl[0][row];
    float m1 = g_pm[1][row], l1 = g_pl[1][row];
    float M  = fmaxf(m0, m1);
    float c0 = __expf(m0 - M);
    float c1 = __expf(m1 - M);
    float inv = 1.0f / fmaf(l0, c0, l1 * c1);

    float2 o0 = *(const float2*)&g_po[0][row * DD + 2 * lane];
    float2 o1 = *(const float2*)&g_po[1][row * DD + 2 * lane];
    *(float2*)&out[row * DD + 2 * lane] =
        make_float2(fmaf(o0.x, c0, o1.x * c1) * inv,
                    fmaf(o0.y, c0, o1.y * c1) * inv);
}

// ---------------------------------------------------------------------------
extern "C" void kernel_launch(void* const* d_in, const int* in_sizes, int n_in,
                              void* d_out, int out_size)
{
    const float* x  = (const float*)d_in[0];
    const float* Wq = (const float*)d_in[1];
    const float* bq = (const float*)d_in[2];
    const float* Wk = (const float*)d_in[3];
    const float* bk = (const float*)d_in[4];
    const float* Wv = (const float*)d_in[5];
    const float* bv = (const float*)d_in[6];
    const float* W1 = (const float*)d_in[7];
    const float* b1 = (const float*)d_in[8];
    const float* W2 = (const float*)d_in[9];
    // b2 (d_in[10]) is a constant shift on scores: cancels in softmax.

    (void)cudaFuncSetAttribute(proj_kernel,
                               cudaFuncAttributeMaxDynamicSharedMemorySize,
                               PROJ_SMEM_BYTES);
    (void)cudaFuncSetAttribute(attn_kernel,
                               cudaFuncAttributeMaxDynamicSharedMemorySize,
                               SMEM_BYTES);

    proj_kernel<<<BB * TT / PROWS, 192, PROJ_SMEM_BYTES>>>(
        x, Wq, bq, Wk, bk, Wv, bv, W1, b1);
    attn_kernel<<<BB * TT / 4 * 2, 64, SMEM_BYTES>>>(W2);
    combine_kernel<<<BB * TT / 4, 128>>>((float*)d_out);
}